// round 15
// baseline (speedup 1.0000x reference)
#include <cuda_runtime.h>
#include <cuda_fp16.h>
#include <math.h>

typedef unsigned int u32;
typedef unsigned long long u64;

#define B_   2
#define S_   2048
#define D_   1024
#define H_   16
#define F_   4096
#define M_   (B_*S_)
#define QKVN 3072

// ------------------------- scratch (device globals) -------------------------
__device__ __align__(16) __half g_xn[M_*D_];
__device__ __align__(16) __half g_qkv[(size_t)M_*QKVN];
__device__ __align__(16) __half g_att[M_*D_];
__device__ __align__(16) float  g_x2[M_*D_];
__device__ __align__(16) __half g_h[(size_t)M_*F_];
__device__ __align__(16) __half g_wqkv16[(size_t)D_*QKVN];  // [K=1024][N=3072]
__device__ __align__(16) float  g_bqkv[QKVN];
__device__ __align__(16) __half g_wo16[D_*D_];              // [K][N] flat
__device__ __align__(16) __half g_w116[(size_t)D_*F_];      // flat
__device__ __align__(16) __half g_w216[(size_t)F_*D_];      // flat

// ------------------------- helpers ------------------------------------------
__device__ __forceinline__ u32 smem_u32(const void* p) {
    u32 a;
    asm("{ .reg .u64 t; cvta.to.shared.u64 t, %1; cvt.u32.u64 %0, t; }"
        : "=r"(a) : "l"(p));
    return a;
}
#define CP_ASYNC16(sm, gp) \
    asm volatile("cp.async.cg.shared.global [%0], [%1], 16;" :: "r"(sm), "l"(gp))
#define CP_ASYNC4(sm, gp) \
    asm volatile("cp.async.ca.shared.global [%0], [%1], 4;" :: "r"(sm), "l"(gp))
#define CP_COMMIT() asm volatile("cp.async.commit_group;" ::: "memory")
#define CP_WAIT(n)  asm volatile("cp.async.wait_group %0;" :: "n"(n) : "memory")

#define LDSM_X4(r0,r1,r2,r3,a) \
    asm volatile("ldmatrix.sync.aligned.m8n8.x4.shared.b16 {%0,%1,%2,%3}, [%4];" \
        : "=r"(r0), "=r"(r1), "=r"(r2), "=r"(r3) : "r"(a))
#define LDSM_X4_T(r0,r1,r2,r3,a) \
    asm volatile("ldmatrix.sync.aligned.m8n8.x4.trans.shared.b16 {%0,%1,%2,%3}, [%4];" \
        : "=r"(r0), "=r"(r1), "=r"(r2), "=r"(r3) : "r"(a))

#define MMA_F16(d, a, b) \
    asm volatile("mma.sync.aligned.m16n8k16.row.col.f32.f16.f16.f32 " \
        "{%0,%1,%2,%3}, {%4,%5,%6,%7}, {%8,%9}, {%0,%1,%2,%3};" \
        : "+f"((d)[0]), "+f"((d)[1]), "+f"((d)[2]), "+f"((d)[3]) \
        : "r"((a)[0]), "r"((a)[1]), "r"((a)[2]), "r"((a)[3]), \
          "r"((b)[0]), "r"((b)[1]))

__device__ __forceinline__ u32 pack_h2(float a, float b) {
    __half2 t = __floats2half2_rn(a, b);
    return *(u32*)&t;
}

// ------------------------- critical-path prologue ----------------------------
__global__ __launch_bounds__(256) void prep_kernel(
    const float* __restrict__ x,  const float* __restrict__ g1,
    const float* __restrict__ be1,
    const float* __restrict__ wq, const float* __restrict__ wk,
    const float* __restrict__ wv,
    const float* __restrict__ bq, const float* __restrict__ bk,
    const float* __restrict__ bv,
    __half* __restrict__ wqkv, float* __restrict__ bqkv,
    __half* __restrict__ xn)
{
    const int job = blockIdx.y;
    const int bx  = blockIdx.x;
    const int tid = threadIdx.x;

    if (job < 3) {
        if (bx >= 2048) return;
        const float* src = (job == 0) ? wq : (job == 1) ? wk : wv;
        const int colOff = job * 1024;
        for (int e = (bx * 256 + tid) * 4; e < (1 << 20); e += 2048 * 1024) {
            const float4 v = *(const float4*)(src + e);
            const int row = e >> 10;
            const int col = e & 1023;
            uint2 pk;
            pk.x = pack_h2(v.x, v.y);
            pk.y = pack_h2(v.z, v.w);
            *(uint2*)(wqkv + (size_t)row * QKVN + colOff + col) = pk;
        }
        return;
    }
    if (job == 3) {
        const int i = bx * 256 + tid;
        if (i >= QKVN) return;
        if (i < 1024)       bqkv[i] = bq[i];
        else if (i < 2048)  bqkv[i] = bk[i - 1024];
        else                bqkv[i] = bv[i - 2048];
        return;
    }

    // job == 4: LayerNorm1, row = bx
    __shared__ float red[8];
    const int row = bx;
    const float* xr = x + (size_t)row * D_;

    float4 xv = *(const float4*)(xr + tid * 4);
    float s = xv.x + xv.y + xv.z + xv.w;
    #pragma unroll
    for (int of = 16; of > 0; of >>= 1) s += __shfl_xor_sync(0xffffffffu, s, of);
    if ((tid & 31) == 0) red[tid >> 5] = s;
    __syncthreads();
    float tot = 0.f;
    #pragma unroll
    for (int w = 0; w < 8; w++) tot += red[w];
    const float mean = tot * (1.0f / D_);

    float d0 = xv.x - mean, d1 = xv.y - mean, d2 = xv.z - mean, d3 = xv.w - mean;
    float sq = d0*d0 + d1*d1 + d2*d2 + d3*d3;
    __syncthreads();
    #pragma unroll
    for (int of = 16; of > 0; of >>= 1) sq += __shfl_xor_sync(0xffffffffu, sq, of);
    if ((tid & 31) == 0) red[tid >> 5] = sq;
    __syncthreads();
    float vtot = 0.f;
    #pragma unroll
    for (int w = 0; w < 8; w++) vtot += red[w];
    const float rstd = rsqrtf(vtot * (1.0f / D_) + 1e-5f);

    float4 gv = *(const float4*)(g1 + tid * 4);
    float4 bv4 = *(const float4*)(be1 + tid * 4);
    const size_t off = (size_t)row * D_ + tid * 4;
    uint2 pk;
    pk.x = pack_h2(d0 * rstd * gv.x + bv4.x, d1 * rstd * gv.y + bv4.y);
    pk.y = pack_h2(d2 * rstd * gv.z + bv4.z, d3 * rstd * gv.w + bv4.w);
    *(uint2*)(xn + off) = pk;
}

// ------------------------- layernorm (fp16 out) ------------------------------
__global__ __launch_bounds__(256) void ln_kernel(
    const float* __restrict__ x, const float* __restrict__ g,
    const float* __restrict__ b, __half* __restrict__ o)
{
    __shared__ float red[8];
    const int row = blockIdx.x;
    const int tid = threadIdx.x;
    const float* xr = x + (size_t)row * D_;

    float4 xv = *(const float4*)(xr + tid * 4);
    float s = xv.x + xv.y + xv.z + xv.w;
    #pragma unroll
    for (int of = 16; of > 0; of >>= 1) s += __shfl_xor_sync(0xffffffffu, s, of);
    if ((tid & 31) == 0) red[tid >> 5] = s;
    __syncthreads();
    float tot = 0.f;
    #pragma unroll
    for (int w = 0; w < 8; w++) tot += red[w];
    const float mean = tot * (1.0f / D_);

    float d0 = xv.x - mean, d1 = xv.y - mean, d2 = xv.z - mean, d3 = xv.w - mean;
    float sq = d0*d0 + d1*d1 + d2*d2 + d3*d3;
    __syncthreads();
    #pragma unroll
    for (int of = 16; of > 0; of >>= 1) sq += __shfl_xor_sync(0xffffffffu, sq, of);
    if ((tid & 31) == 0) red[tid >> 5] = sq;
    __syncthreads();
    float vtot = 0.f;
    #pragma unroll
    for (int w = 0; w < 8; w++) vtot += red[w];
    const float rstd = rsqrtf(vtot * (1.0f / D_) + 1e-5f);

    float4 gv = *(const float4*)(g + tid * 4);
    float4 bv = *(const float4*)(b + tid * 4);
    const size_t off = (size_t)row * D_ + tid * 4;
    uint2 pk;
    pk.x = pack_h2(d0 * rstd * gv.x + bv.x, d1 * rstd * gv.y + bv.y);
    pk.y = pack_h2(d2 * rstd * gv.z + bv.z, d3 * rstd * gv.w + bv.w);
    *(uint2*)(o + off) = pk;
}

// ------------------------- fp16 HMMA GEMM (256 thr, 128x128 tile) ------------
#define ATROWB 144
#define ATILE  (128*ATROWB)        // 18432
#define BROWB  272
#define BTILE  (64*BROWB)          // 17408
#define STAGEB (ATILE + BTILE)     // 35840
#define GSMEM  (2*STAGEB)          // 71680

template<int OUT, bool RELU, bool RES, bool QKVA>
__global__ __launch_bounds__(256, 2) void h16_gemm(
    const __half* __restrict__ A, const __half* __restrict__ Bw,
    const float* __restrict__ bias, const float* __restrict__ res,
    float* __restrict__ C, __half* __restrict__ Cb,
    const float* __restrict__ cw0, const float* __restrict__ cw1,
    const float* __restrict__ cw2,
    __half* __restrict__ cd0, __half* __restrict__ cd1,
    __half* __restrict__ cd2,
    int M, int N, int K)
{
    extern __shared__ char smem[];
    const u32 sbase = smem_u32(smem);

    const int tid = threadIdx.x;

    if (QKVA && (int)blockIdx.y >= (M >> 7)) {
        const int cb   = ((int)blockIdx.y - (M >> 7)) * gridDim.x + blockIdx.x;
        const int step = 96 * 256 * 4;
        const int t0   = (cb * 256 + tid) * 4;
        for (int e = t0; e < (1 << 20); e += step) {
            const float4 v = *(const float4*)(cw0 + e);
            uint2 pk; pk.x = pack_h2(v.x, v.y); pk.y = pack_h2(v.z, v.w);
            *(uint2*)(cd0 + e) = pk;
        }
        for (int e = t0; e < (1 << 22); e += step) {
            const float4 v = *(const float4*)(cw1 + e);
            uint2 pk; pk.x = pack_h2(v.x, v.y); pk.y = pack_h2(v.z, v.w);
            *(uint2*)(cd1 + e) = pk;
        }
        for (int e = t0; e < (1 << 22); e += step) {
            const float4 v = *(const float4*)(cw2 + e);
            uint2 pk; pk.x = pack_h2(v.x, v.y); pk.y = pack_h2(v.z, v.w);
            *(uint2*)(cd2 + e) = pk;
        }
        return;
    }

    const int wid = tid >> 5;
    const int lid = tid & 31;
    const int wr  = wid & 1;
    const int wc  = wid >> 1;
    const int bm  = blockIdx.y * 128;
    const int bn  = blockIdx.x * 128;

    const int nch = K >> 6;

    auto load_chunk = [&](int i, int st) {
        const size_t kc = (size_t)i * 64;
        const u32 so = sbase + st * STAGEB;
        #pragma unroll
        for (int it = 0; it < 4; it++) {
            const int idx = tid + it * 256;
            const int r = idx >> 3, seg = idx & 7;
            const __half* gp = A + (size_t)(bm + r) * K + kc + seg * 8;
            CP_ASYNC16(so + r * ATROWB + seg * 16, gp);
        }
        #pragma unroll
        for (int it = 0; it < 4; it++) {
            const int idx = tid + it * 256;
            const int r = idx >> 4, seg = idx & 15;
            const __half* gp = Bw + (kc + r) * (size_t)N + bn + seg * 8;
            CP_ASYNC16(so + ATILE + r * BROWB + seg * 16, gp);
        }
        CP_COMMIT();
    };

    float acc[4][4][4];
    #pragma unroll
    for (int i = 0; i < 4; i++)
        #pragma unroll
        for (int j = 0; j < 4; j++)
            #pragma unroll
            for (int f = 0; f < 4; f++) acc[i][j][f] = 0.f;

    const u32 a_lane = (u32)((wr*64 + (lid & 15)) * ATROWB + (lid >> 4) * 16);
    const u32 b_lane = (u32)((lid & 15) * BROWB + (lid >> 4) * 16 + wc * 64);

    load_chunk(0, 0);

    for (int i = 0; i < nch; i++) {
        const int st = i & 1;
        CP_WAIT(0);
        __syncthreads();
        if (i + 1 < nch) load_chunk(i + 1, st ^ 1);

        const u32 so = sbase + st * STAGEB;
        const u32 aB = so + a_lane;
        const u32 bB = so + ATILE + b_lane;

        #pragma unroll
        for (int ks = 0; ks < 4; ks++) {
            u32 fa[4][4];
            #pragma unroll
            for (int am = 0; am < 4; am++)
                LDSM_X4(fa[am][0], fa[am][1], fa[am][2], fa[am][3],
                        aB + am * (16*ATROWB) + ks * 32);
            u32 fb[4][2];
            #pragma unroll
            for (int ns = 0; ns < 2; ns++) {
                u32 r0, r1, r2, r3;
                LDSM_X4_T(r0, r1, r2, r3, bB + ks * (16*BROWB) + ns * 32);
                fb[ns*2  ][0] = r0; fb[ns*2  ][1] = r1;
                fb[ns*2+1][0] = r2; fb[ns*2+1][1] = r3;
            }
            #pragma unroll
            for (int am = 0; am < 4; am++)
                #pragma unroll
                for (int nt = 0; nt < 4; nt++)
                    MMA_F16(acc[am][nt], fa[am], fb[nt]);
        }
    }

    const int r0 = bm + wr*64 + (lid >> 2);
    const int c0 = bn + wc*32 + (lid & 3) * 2;
    #pragma unroll
    for (int am = 0; am < 4; am++) {
        #pragma unroll
        for (int bt = 0; bt < 4; bt++) {
            const int col = c0 + bt * 8;
            const float2 bv = *(const float2*)(bias + col);
            const float alpha = QKVA ? ((col < 1024) ? 0.125f : 1.0f) : 1.0f;
            #pragma unroll
            for (int half = 0; half < 2; half++) {
                const int row = r0 + am*16 + half*8;
                float v0 = (acc[am][bt][half*2 + 0] + bv.x) * alpha;
                float v1 = (acc[am][bt][half*2 + 1] + bv.y) * alpha;
                if (RELU) { v0 = fmaxf(v0, 0.f); v1 = fmaxf(v1, 0.f); }
                if (RES) {
                    const float2 rr = *(const float2*)(res + (size_t)row * N + col);
                    v0 += rr.x; v1 += rr.y;
                }
                if (OUT == 2) {
                    *(u32*)(Cb + (size_t)row * N + col) = pack_h2(v0, v1);
                } else {
                    float2 o; o.x = v0; o.y = v1;
                    *(float2*)(C + (size_t)row * N + col) = o;
                }
            }
        }
    }
}

// ------------------------- fp16 HMMA GEMM (128 thr, 64x128 tile) -------------
// 4 warps, each the same 64x32 warp tile; 4 CTAs/SM -> balanced waves for
// small-grid N=1024 GEMMs (O-proj, FFN2). Math identical to h16_gemm.
#define A64TILE (64*ATROWB)          // 9216
#define ST64B   (A64TILE + BTILE)    // 26624
#define GSMEM64 (2*ST64B)            // 53248

template<int OUT, bool RELU, bool RES>
__global__ __launch_bounds__(128, 4) void h16_gemm_m64(
    const __half* __restrict__ A, const __half* __restrict__ Bw,
    const float* __restrict__ bias, const float* __restrict__ res,
    float* __restrict__ C, __half* __restrict__ Cb, int M, int N, int K)
{
    extern __shared__ char smem[];
    const u32 sbase = smem_u32(smem);

    const int tid = threadIdx.x;
    const int wid = tid >> 5;     // 0..3 -> 32-col group
    const int lid = tid & 31;
    const int bm  = blockIdx.y * 64;
    const int bn  = blockIdx.x * 128;

    const int nch = K >> 6;

    auto load_chunk = [&](int i, int st) {
        const size_t kc = (size_t)i * 64;
        const u32 so = sbase + st * ST64B;
        // A tile: 64 rows x 8 segs = 512 segs / 128 thr = 4 each
        #pragma unroll
        for (int it = 0; it < 4; it++) {
            const int idx = tid + it * 128;
            const int r = idx >> 3, seg = idx & 7;
            const __half* gp = A + (size_t)(bm + r) * K + kc + seg * 8;
            CP_ASYNC16(so + r * ATROWB + seg * 16, gp);
        }
        // B tile: 64 k-rows x 16 segs = 1024 segs / 128 thr = 8 each
        #pragma unroll
        for (int it = 0; it < 8; it++) {
            const int idx = tid + it * 128;
            const int r = idx >> 4, seg = idx & 15;
            const __half* gp = Bw + (kc + r) * (size_t)N + bn + seg * 8;
            CP_ASYNC16(so + A64TILE + r * BROWB + seg * 16, gp);
        }
        CP_COMMIT();
    };

    float acc[4][4][4];
    #pragma unroll
    for (int i = 0; i < 4; i++)
        #pragma unroll
        for (int j = 0; j < 4; j++)
            #pragma unroll
            for (int f = 0; f < 4; f++) acc[i][j][f] = 0.f;

    const u32 a_lane = (u32)(((lid & 15)) * ATROWB + (lid >> 4) * 16);
    const u32 b_lane = (u32)((lid & 15) * BROWB + (lid >> 4) * 16 + wid * 64);

    load_chunk(0, 0);

    for (int i = 0; i < nch; i++) {
        const int st = i & 1;
        CP_WAIT(0);
        __syncthreads();
        if (i + 1 < nch) load_chunk(i + 1, st ^ 1);

        const u32 so = sbase + st * ST64B;
        const u32 aB = so + a_lane;
        const u32 bB = so + A64TILE + b_lane;

        #pragma unroll
        for (int ks = 0; ks < 4; ks++) {
            u32 fa[4][4];
            #pragma unroll
            for (int am = 0; am < 4; am++)
                LDSM_X4(fa[am][0], fa[am][1], fa[am][2], fa[am][3],
                        aB + am * (16*ATROWB) + ks * 32);
            u32 fb[4][2];
            #pragma unroll
            for (int ns = 0; ns < 2; ns++) {
                u32 r0, r1, r2, r3;
                LDSM_X4_T(r0, r1, r2, r3, bB + ks * (16*BROWB) + ns * 32);
                fb[ns*2  ][0] = r0; fb[ns*2  ][1] = r1;
                fb[ns*2+1][0] = r2; fb[ns*2+1][1] = r3;
            }
            #pragma unroll
            for (int am = 0; am < 4; am++)
                #pragma unroll
                for (int nt = 0; nt < 4; nt++)
                    MMA_F16(acc[am][nt], fa[am], fb[nt]);
        }
    }

    const int r0 = bm + (lid >> 2);
    const int c0 = bn + wid*32 + (lid & 3) * 2;
    #pragma unroll
    for (int am = 0; am < 4; am++) {
        #pragma unroll
        for (int bt = 0; bt < 4; bt++) {
            const int col = c0 + bt * 8;
            const float2 bv = *(const float2*)(bias + col);
            #pragma unroll
            for (int half = 0; half < 2; half++) {
                const int row = r0 + am*16 + half*8;
                float v0 = acc[am][bt][half*2 + 0] + bv.x;
                float v1 = acc[am][bt][half*2 + 1] + bv.y;
                if (RELU) { v0 = fmaxf(v0, 0.f); v1 = fmaxf(v1, 0.f); }
                if (RES) {
                    const float2 rr = *(const float2*)(res + (size_t)row * N + col);
                    v0 += rr.x; v1 += rr.y;
                }
                if (OUT == 2) {
                    *(u32*)(Cb + (size_t)row * N + col) = pack_h2(v0, v1);
                } else {
                    float2 o; o.x = v0; o.y = v1;
                    *(float2*)(C + (size_t)row * N + col) = o;
                }
            }
        }
    }
}

// ------------------------- fp16 HMMA flash attention -------------------------
#define AQ_OFF   0
#define AK_OFF(st) (9216 + (st)*9216)
#define AV_OFF(st) (27648 + (st)*9216)
#define AM_OFF(st) (46080 + (st)*256)
#define ASMEM    46592

__global__ __launch_bounds__(128, 4) void attn_mma_kernel(
    const __half* __restrict__ QKV, const int* __restrict__ mask,
    __half* __restrict__ O)
{
    extern __shared__ char sm[];
    const u32 sb = smem_u32(sm);
    const int tid = threadIdx.x;
    const int wid = tid >> 5;
    const int lid = tid & 31;
    const int h = blockIdx.y;
    const int b = blockIdx.z;
    const size_t qrow0 = (size_t)(b * S_ + blockIdx.x * 64);

    const __half* Q = QKV;
    const __half* K = QKV + 1024;
    const __half* V = QKV + 2048;

    #pragma unroll
    for (int it = 0; it < 4; it++) {
        const int t = tid + it * 128;
        const int r = t >> 3, cseg = t & 7;
        const uint4 v = *(const uint4*)(Q + (qrow0 + r) * QKVN + h * 64 + cseg * 8);
        *(uint4*)(sm + AQ_OFF + r * 144 + cseg * 16) = v;
    }

    auto load_kv = [&](int jt, int st) {
        const size_t krow0 = (size_t)(b * S_ + jt * 64);
        #pragma unroll
        for (int it = 0; it < 8; it++) {
            const int t = tid + it * 128;
            const int tile = t >> 9;
            const int r = (t >> 3) & 63;
            const int cseg = t & 7;
            const __half* src = (tile ? V : K) + (krow0 + r) * QKVN + h * 64 + cseg * 8;
            const u32 dst = sb + (tile ? AV_OFF(st) : AK_OFF(st)) + (u32)(r * 144 + cseg * 16);
            CP_ASYNC16(dst, src);
        }
        if (tid < 64)
            CP_ASYNC4(sb + AM_OFF(st) + tid * 4, mask + b * S_ + jt * 64 + tid);
        CP_COMMIT();
    };

    load_kv(0, 0);
    __syncthreads();

    u32 qf[4][4];
    const u32 qaddr = sb + AQ_OFF + (u32)((wid * 16 + (lid & 15)) * 144 + (lid >> 4) * 16);
    #pragma unroll
    for (int ks = 0; ks < 4; ks++)
        LDSM_X4(qf[ks][0], qf[ks][1], qf[ks][2], qf[ks][3], qaddr + ks * 32);

    float m0 = -INFINITY, m1 = -INFINITY, l0 = 0.f, l1 = 0.f;
    float o[8][4];
    #pragma unroll
    for (int t = 0; t < 8; t++)
        #pragma unroll
        for (int f = 0; f < 4; f++) o[t][f] = 0.f;

    const int ntiles = S_ / 64;
    for (int jt = 0; jt < ntiles; jt++) {
        const int st = jt & 1;
        CP_WAIT(0);
        __syncthreads();
        if (jt + 1 < ntiles) load_kv(jt + 1, st ^ 1);

        float s[8][4];
        #pragma unroll
        for (int t = 0; t < 8; t++)
            #pragma unroll
            for (int f = 0; f < 4; f++) s[t][f] = 0.f;

        const u32 kaddr = sb + AK_OFF(st) + (u32)(((lid & 15)) * 144 + (lid >> 4) * 16);
        #pragma unroll
        for (int ks = 0; ks < 4; ks++) {
            #pragma unroll
            for (int nt2 = 0; nt2 < 4; nt2++) {
                u32 r0, r1, r2, r3;
                LDSM_X4(r0, r1, r2, r3, kaddr + nt2 * (16*144) + ks * 32);
                u32 bA[2] = {r0, r2};
                u32 bB[2] = {r1, r3};
                MMA_F16(s[nt2*2],     qf[ks], bA);
                MMA_F16(s[nt2*2 + 1], qf[ks], bB);
            }
        }

        float mx0 = -INFINITY, mx1 = -INFINITY;
        #pragma unroll
        for (int t = 0; t < 8; t++) {
            const int mi_a = *(const int*)(sm + AM_OFF(st) + (t*8 + (lid & 3)*2) * 4);
            const int mi_b = *(const int*)(sm + AM_OFF(st) + (t*8 + (lid & 3)*2 + 1) * 4);
            const float ma = mi_a ? 0.f : -1e9f;
            const float mb = mi_b ? 0.f : -1e9f;
            s[t][0] += ma; s[t][1] += mb; s[t][2] += ma; s[t][3] += mb;
            mx0 = fmaxf(mx0, fmaxf(s[t][0], s[t][1]));
            mx1 = fmaxf(mx1, fmaxf(s[t][2], s[t][3]));
        }
        mx0 = fmaxf(mx0, __shfl_xor_sync(0xffffffffu, mx0, 1));
        mx0 = fmaxf(mx0, __shfl_xor_sync(0xffffffffu, mx0, 2));
        mx1 = fmaxf(mx1, __shfl_xor_sync(0xffffffffu, mx1, 1));
        mx1 = fmaxf(mx1, __shfl_xor_sync(0xffffffffu, mx1, 2));

        const float nm0 = fmaxf(m0, mx0);
        const float nm1 = fmaxf(m1, mx1);
        const float f0 = __expf(m0 - nm0);
        const float f1 = __expf(m1 - nm1);
        m0 = nm0; m1 = nm1;
        l0 *= f0;  l1 *= f1;
        #pragma unroll
        for (int t = 0; t < 8; t++) {
            o[t][0] *= f0; o[t][1] *= f0;
            o[t][2] *= f1; o[t][3] *= f1;
        }

        u32 pa[4][4];
        float ps0 = 0.f, ps1 = 0.f;
        #pragma unroll
        for (int t = 0; t < 8; t++) {
            const float p0 = __expf(s[t][0] - m0);
            const float p1 = __expf(s[t][1] - m0);
            const float p2 = __expf(s[t][2] - m1);
            const float p3 = __expf(s[t][3] - m1);
            ps0 += p0 + p1; ps1 += p2 + p3;
            pa[t >> 1][(t & 1) * 2]     = pack_h2(p0, p1);
            pa[t >> 1][(t & 1) * 2 + 1] = pack_h2(p2, p3);
        }
        ps0 += __shfl_xor_sync(0xffffffffu, ps0, 1);
        ps0 += __shfl_xor_sync(0xffffffffu, ps0, 2);
        ps1 += __shfl_xor_sync(0xffffffffu, ps1, 1);
        ps1 += __shfl_xor_sync(0xffffffffu, ps1, 2);
        l0 += ps0; l1 += ps1;

        const u32 vaddr = sb + AV_OFF(st) + (u32)(((lid & 15)) * 144 + (lid >> 4) * 16);
        #pragma unroll
        for (int ks = 0; ks < 4; ks++) {
            #pragma unroll
            for (int dt2 = 0; dt2 < 4; dt2++) {
                u32 r0, r1, r2, r3;
                LDSM_X4_T(r0, r1, r2, r3, vaddr + ks * (16*144) + dt2 * 32);
                u32 bA[2] = {r0, r1};
                u32 bB[2] = {r2, r3};
                MMA_F16(o[dt2*2],     pa[ks], bA);
                MMA_F16(o[dt2*2 + 1], pa[ks], bB);
            }
        }
    }

    const float inv0 = (l0 > 0.f) ? 1.f / l0 : 0.f;
    const float inv1 = (l1 > 0.f) ? 1.f / l1 : 0.f;
    const size_t row0 = qrow0 + wid * 16 + (lid >> 2);
    const int colb = h * 64 + (lid & 3) * 2;
    #pragma unroll
    for (int t = 0; t < 8; t++) {
        const int col = colb + t * 8;
        *(u32*)(O + row0 * D_ + col)       = pack_h2(o[t][0] * inv0, o[t][1] * inv0);
        *(u32*)(O + (row0 + 8) * D_ + col) = pack_h2(o[t][2] * inv1, o[t][3] * inv1);
    }
}

// ------------------------- launch -------------------------------------------
extern "C" void kernel_launch(void* const* d_in, const int* in_sizes, int n_in,
                              void* d_out, int out_size)
{
    const float* x    = (const float*)d_in[0];
    const int*   mask = (const int*)  d_in[1];
    const float* wq   = (const float*)d_in[2];
    const float* bq   = (const float*)d_in[3];
    const float* wk   = (const float*)d_in[4];
    const float* bk   = (const float*)d_in[5];
    const float* wv   = (const float*)d_in[6];
    const float* bv   = (const float*)d_in[7];
    const float* wo   = (const float*)d_in[8];
    const float* bo   = (const float*)d_in[9];
    const float* g1   = (const float*)d_in[10];
    const float* be1  = (const float*)d_in[11];
    const float* g2   = (const float*)d_in[12];
    const float* be2  = (const float*)d_in[13];
    const float* w1   = (const float*)d_in[14];
    const float* bf1  = (const float*)d_in[15];
    const float* w2   = (const float*)d_in[16];
    const float* bf2  = (const float*)d_in[17];
    float* out = (float*)d_out;

    void* p;
    cudaGetSymbolAddress(&p, g_xn);     __half* xn     = (__half*)p;
    cudaGetSymbolAddress(&p, g_qkv);    __half* qkv    = (__half*)p;
    cudaGetSymbolAddress(&p, g_att);    __half* att    = (__half*)p;
    cudaGetSymbolAddress(&p, g_x2);     float*  x2     = (float*)p;
    cudaGetSymbolAddress(&p, g_h);      __half* hb     = (__half*)p;
    cudaGetSymbolAddress(&p, g_wqkv16); __half* wqkv16 = (__half*)p;
    cudaGetSymbolAddress(&p, g_bqkv);   float*  bqkv   = (float*)p;
    cudaGetSymbolAddress(&p, g_wo16);   __half* wo16   = (__half*)p;
    cudaGetSymbolAddress(&p, g_w116);   __half* w116   = (__half*)p;
    cudaGetSymbolAddress(&p, g_w216);   __half* w216   = (__half*)p;

    cudaFuncSetAttribute(h16_gemm<2,false,false,true >, cudaFuncAttributeMaxDynamicSharedMemorySize, GSMEM);
    cudaFuncSetAttribute(h16_gemm<2,true ,false,false>, cudaFuncAttributeMaxDynamicSharedMemorySize, GSMEM);
    cudaFuncSetAttribute(h16_gemm_m64<0,false,true>, cudaFuncAttributeMaxDynamicSharedMemorySize, GSMEM64);
    cudaFuncSetAttribute(attn_mma_kernel, cudaFuncAttributeMaxDynamicSharedMemorySize, ASMEM);

    // critical-path prologue: wqkv convert + bias pack + LN1
    prep_kernel<<<dim3(4096, 5), 256>>>(x, g1, be1, wq, wk, wv, bq, bk, bv,
                                        wqkv16, bqkv, xn);

    // fused QKV GEMM (Q cols pre-scaled by 1/8) + tail-wave wo/w1/w2 conversion
    const dim3 gQKV(QKVN/128, M_/128 + 4);
    h16_gemm<2,false,false,true><<<gQKV, 256, GSMEM>>>(
        xn, wqkv16, bqkv, nullptr, nullptr, qkv,
        wo, w1, w2, wo16, w116, w216, M_, QKVN, D_);

    // attention: 64-q-row CTAs, 1024 total (4 CTAs/SM)
    dim3 attG(S_/64, H_, B_);
    attn_mma_kernel<<<attG, 128, ASMEM>>>(qkv, mask, att);

    // O projection + residual(x): M64 tiles -> 512 CTAs, balanced wave
    const dim3 gO(D_/128, M_/64);
    h16_gemm_m64<0,false,true><<<gO, 128, GSMEM64>>>(
        att, wo16, bo, x, x2, nullptr, M_, D_, D_);

    ln_kernel<<<M_, 256>>>(x2, g2, be2, xn);

    const dim3 gF(F_/128, M_/128);
    h16_gemm<2,true,false,false><<<gF, 256, GSMEM>>>(
        xn, w116, bf1, nullptr, nullptr, hb,
        nullptr, nullptr, nullptr, nullptr, nullptr, nullptr, M_, F_, D_);

    // FFN2 + residual(x2): M64 tiles -> 512 CTAs
    h16_gemm_m64<0,false,true><<<gO, 128, GSMEM64>>>(
        hb, w216, bf2, x2, out, nullptr, M_, D_, F_);
}

// round 16
// speedup vs baseline: 1.0097x; 1.0097x over previous
#include <cuda_runtime.h>
#include <cuda_fp16.h>
#include <math.h>

typedef unsigned int u32;
typedef unsigned long long u64;

#define B_   2
#define S_   2048
#define D_   1024
#define H_   16
#define F_   4096
#define M_   (B_*S_)
#define QKVN 3072

// ------------------------- scratch (device globals) -------------------------
__device__ __align__(16) __half g_xn[M_*D_];
__device__ __align__(16) __half g_qkv[(size_t)M_*QKVN];
__device__ __align__(16) __half g_att[M_*D_];
__device__ __align__(16) float  g_x2[M_*D_];
__device__ __align__(16) __half g_h[(size_t)M_*F_];
__device__ __align__(16) __half g_wqkv16[(size_t)D_*QKVN];  // [K=1024][N=3072]
__device__ __align__(16) float  g_bqkv[QKVN];
__device__ __align__(16) __half g_wo16[D_*D_];              // [K][N] flat
__device__ __align__(16) __half g_w116[(size_t)D_*F_];      // flat
__device__ __align__(16) __half g_w216[(size_t)F_*D_];      // flat

// ------------------------- helpers ------------------------------------------
__device__ __forceinline__ u32 smem_u32(const void* p) {
    u32 a;
    asm("{ .reg .u64 t; cvta.to.shared.u64 t, %1; cvt.u32.u64 %0, t; }"
        : "=r"(a) : "l"(p));
    return a;
}
#define CP_ASYNC16(sm, gp) \
    asm volatile("cp.async.cg.shared.global [%0], [%1], 16;" :: "r"(sm), "l"(gp))
#define CP_ASYNC4(sm, gp) \
    asm volatile("cp.async.ca.shared.global [%0], [%1], 4;" :: "r"(sm), "l"(gp))
#define CP_COMMIT() asm volatile("cp.async.commit_group;" ::: "memory")
#define CP_WAIT(n)  asm volatile("cp.async.wait_group %0;" :: "n"(n) : "memory")

#define LDSM_X4(r0,r1,r2,r3,a) \
    asm volatile("ldmatrix.sync.aligned.m8n8.x4.shared.b16 {%0,%1,%2,%3}, [%4];" \
        : "=r"(r0), "=r"(r1), "=r"(r2), "=r"(r3) : "r"(a))
#define LDSM_X4_T(r0,r1,r2,r3,a) \
    asm volatile("ldmatrix.sync.aligned.m8n8.x4.trans.shared.b16 {%0,%1,%2,%3}, [%4];" \
        : "=r"(r0), "=r"(r1), "=r"(r2), "=r"(r3) : "r"(a))

#define MMA_F16(d, a, b) \
    asm volatile("mma.sync.aligned.m16n8k16.row.col.f32.f16.f16.f32 " \
        "{%0,%1,%2,%3}, {%4,%5,%6,%7}, {%8,%9}, {%0,%1,%2,%3};" \
        : "+f"((d)[0]), "+f"((d)[1]), "+f"((d)[2]), "+f"((d)[3]) \
        : "r"((a)[0]), "r"((a)[1]), "r"((a)[2]), "r"((a)[3]), \
          "r"((b)[0]), "r"((b)[1]))

__device__ __forceinline__ u32 pack_h2(float a, float b) {
    __half2 t = __floats2half2_rn(a, b);
    return *(u32*)&t;
}

// ------------------------- critical-path prologue ----------------------------
__global__ __launch_bounds__(256) void prep_kernel(
    const float* __restrict__ x,  const float* __restrict__ g1,
    const float* __restrict__ be1,
    const float* __restrict__ wq, const float* __restrict__ wk,
    const float* __restrict__ wv,
    const float* __restrict__ bq, const float* __restrict__ bk,
    const float* __restrict__ bv,
    __half* __restrict__ wqkv, float* __restrict__ bqkv,
    __half* __restrict__ xn)
{
    const int job = blockIdx.y;
    const int bx  = blockIdx.x;
    const int tid = threadIdx.x;

    if (job < 3) {
        if (bx >= 2048) return;
        const float* src = (job == 0) ? wq : (job == 1) ? wk : wv;
        const int colOff = job * 1024;
        for (int e = (bx * 256 + tid) * 4; e < (1 << 20); e += 2048 * 1024) {
            const float4 v = *(const float4*)(src + e);
            const int row = e >> 10;
            const int col = e & 1023;
            uint2 pk;
            pk.x = pack_h2(v.x, v.y);
            pk.y = pack_h2(v.z, v.w);
            *(uint2*)(wqkv + (size_t)row * QKVN + colOff + col) = pk;
        }
        return;
    }
    if (job == 3) {
        const int i = bx * 256 + tid;
        if (i >= QKVN) return;
        if (i < 1024)       bqkv[i] = bq[i];
        else if (i < 2048)  bqkv[i] = bk[i - 1024];
        else                bqkv[i] = bv[i - 2048];
        return;
    }

    // job == 4: LayerNorm1, row = bx
    __shared__ float red[8];
    const int row = bx;
    const float* xr = x + (size_t)row * D_;

    float4 xv = *(const float4*)(xr + tid * 4);
    float s = xv.x + xv.y + xv.z + xv.w;
    #pragma unroll
    for (int of = 16; of > 0; of >>= 1) s += __shfl_xor_sync(0xffffffffu, s, of);
    if ((tid & 31) == 0) red[tid >> 5] = s;
    __syncthreads();
    float tot = 0.f;
    #pragma unroll
    for (int w = 0; w < 8; w++) tot += red[w];
    const float mean = tot * (1.0f / D_);

    float d0 = xv.x - mean, d1 = xv.y - mean, d2 = xv.z - mean, d3 = xv.w - mean;
    float sq = d0*d0 + d1*d1 + d2*d2 + d3*d3;
    __syncthreads();
    #pragma unroll
    for (int of = 16; of > 0; of >>= 1) sq += __shfl_xor_sync(0xffffffffu, sq, of);
    if ((tid & 31) == 0) red[tid >> 5] = sq;
    __syncthreads();
    float vtot = 0.f;
    #pragma unroll
    for (int w = 0; w < 8; w++) vtot += red[w];
    const float rstd = rsqrtf(vtot * (1.0f / D_) + 1e-5f);

    float4 gv = *(const float4*)(g1 + tid * 4);
    float4 bv4 = *(const float4*)(be1 + tid * 4);
    const size_t off = (size_t)row * D_ + tid * 4;
    uint2 pk;
    pk.x = pack_h2(d0 * rstd * gv.x + bv4.x, d1 * rstd * gv.y + bv4.y);
    pk.y = pack_h2(d2 * rstd * gv.z + bv4.z, d3 * rstd * gv.w + bv4.w);
    *(uint2*)(xn + off) = pk;
}

// ------------------------- layernorm (fp16 out) ------------------------------
__global__ __launch_bounds__(256) void ln_kernel(
    const float* __restrict__ x, const float* __restrict__ g,
    const float* __restrict__ b, __half* __restrict__ o)
{
    __shared__ float red[8];
    const int row = blockIdx.x;
    const int tid = threadIdx.x;
    const float* xr = x + (size_t)row * D_;

    float4 xv = *(const float4*)(xr + tid * 4);
    float s = xv.x + xv.y + xv.z + xv.w;
    #pragma unroll
    for (int of = 16; of > 0; of >>= 1) s += __shfl_xor_sync(0xffffffffu, s, of);
    if ((tid & 31) == 0) red[tid >> 5] = s;
    __syncthreads();
    float tot = 0.f;
    #pragma unroll
    for (int w = 0; w < 8; w++) tot += red[w];
    const float mean = tot * (1.0f / D_);

    float d0 = xv.x - mean, d1 = xv.y - mean, d2 = xv.z - mean, d3 = xv.w - mean;
    float sq = d0*d0 + d1*d1 + d2*d2 + d3*d3;
    __syncthreads();
    #pragma unroll
    for (int of = 16; of > 0; of >>= 1) sq += __shfl_xor_sync(0xffffffffu, sq, of);
    if ((tid & 31) == 0) red[tid >> 5] = sq;
    __syncthreads();
    float vtot = 0.f;
    #pragma unroll
    for (int w = 0; w < 8; w++) vtot += red[w];
    const float rstd = rsqrtf(vtot * (1.0f / D_) + 1e-5f);

    float4 gv = *(const float4*)(g + tid * 4);
    float4 bv = *(const float4*)(b + tid * 4);
    const size_t off = (size_t)row * D_ + tid * 4;
    uint2 pk;
    pk.x = pack_h2(d0 * rstd * gv.x + bv.x, d1 * rstd * gv.y + bv.y);
    pk.y = pack_h2(d2 * rstd * gv.z + bv.z, d3 * rstd * gv.w + bv.w);
    *(uint2*)(o + off) = pk;
}

// ------------------------- fp16 HMMA GEMM (256 thr, 128x128 tile) ------------
// QKVA variant: blocks with blockIdx.y >= M/128 are tail-wave converter blocks
// (120 total) that flat-convert wo/w1/w2 fp32 -> fp16 and exit.
#define ATROWB 144
#define ATILE  (128*ATROWB)        // 18432
#define BROWB  272
#define BTILE  (64*BROWB)          // 17408
#define STAGEB (ATILE + BTILE)     // 35840
#define GSMEM  (2*STAGEB)          // 71680
#define NCONV  120

template<int OUT, bool RELU, bool RES, bool QKVA>
__global__ __launch_bounds__(256, 2) void h16_gemm(
    const __half* __restrict__ A, const __half* __restrict__ Bw,
    const float* __restrict__ bias, const float* __restrict__ res,
    float* __restrict__ C, __half* __restrict__ Cb,
    const float* __restrict__ cw0, const float* __restrict__ cw1,
    const float* __restrict__ cw2,
    __half* __restrict__ cd0, __half* __restrict__ cd1,
    __half* __restrict__ cd2,
    int M, int N, int K)
{
    extern __shared__ char smem[];
    const u32 sbase = smem_u32(smem);

    const int tid = threadIdx.x;

    if (QKVA && (int)blockIdx.y >= (M >> 7)) {
        const int cb   = ((int)blockIdx.y - (M >> 7)) * gridDim.x + blockIdx.x;
        if (cb >= NCONV) return;
        const int step = NCONV * 256 * 4;
        const int t0   = (cb * 256 + tid) * 4;
        for (int e = t0; e < (1 << 20); e += step) {
            const float4 v = *(const float4*)(cw0 + e);
            uint2 pk; pk.x = pack_h2(v.x, v.y); pk.y = pack_h2(v.z, v.w);
            *(uint2*)(cd0 + e) = pk;
        }
        for (int e = t0; e < (1 << 22); e += step) {
            const float4 v = *(const float4*)(cw1 + e);
            uint2 pk; pk.x = pack_h2(v.x, v.y); pk.y = pack_h2(v.z, v.w);
            *(uint2*)(cd1 + e) = pk;
        }
        for (int e = t0; e < (1 << 22); e += step) {
            const float4 v = *(const float4*)(cw2 + e);
            uint2 pk; pk.x = pack_h2(v.x, v.y); pk.y = pack_h2(v.z, v.w);
            *(uint2*)(cd2 + e) = pk;
        }
        return;
    }

    const int wid = tid >> 5;
    const int lid = tid & 31;
    const int wr  = wid & 1;
    const int wc  = wid >> 1;
    const int bm  = blockIdx.y * 128;
    const int bn  = blockIdx.x * 128;

    const int nch = K >> 6;

    auto load_chunk = [&](int i, int st) {
        const size_t kc = (size_t)i * 64;
        const u32 so = sbase + st * STAGEB;
        #pragma unroll
        for (int it = 0; it < 4; it++) {
            const int idx = tid + it * 256;
            const int r = idx >> 3, seg = idx & 7;
            const __half* gp = A + (size_t)(bm + r) * K + kc + seg * 8;
            CP_ASYNC16(so + r * ATROWB + seg * 16, gp);
        }
        #pragma unroll
        for (int it = 0; it < 4; it++) {
            const int idx = tid + it * 256;
            const int r = idx >> 4, seg = idx & 15;
            const __half* gp = Bw + (kc + r) * (size_t)N + bn + seg * 8;
            CP_ASYNC16(so + ATILE + r * BROWB + seg * 16, gp);
        }
        CP_COMMIT();
    };

    float acc[4][4][4];
    #pragma unroll
    for (int i = 0; i < 4; i++)
        #pragma unroll
        for (int j = 0; j < 4; j++)
            #pragma unroll
            for (int f = 0; f < 4; f++) acc[i][j][f] = 0.f;

    const u32 a_lane = (u32)((wr*64 + (lid & 15)) * ATROWB + (lid >> 4) * 16);
    const u32 b_lane = (u32)((lid & 15) * BROWB + (lid >> 4) * 16 + wc * 64);

    load_chunk(0, 0);

    for (int i = 0; i < nch; i++) {
        const int st = i & 1;
        CP_WAIT(0);
        __syncthreads();
        if (i + 1 < nch) load_chunk(i + 1, st ^ 1);

        const u32 so = sbase + st * STAGEB;
        const u32 aB = so + a_lane;
        const u32 bB = so + ATILE + b_lane;

        #pragma unroll
        for (int ks = 0; ks < 4; ks++) {
            u32 fa[4][4];
            #pragma unroll
            for (int am = 0; am < 4; am++)
                LDSM_X4(fa[am][0], fa[am][1], fa[am][2], fa[am][3],
                        aB + am * (16*ATROWB) + ks * 32);
            u32 fb[4][2];
            #pragma unroll
            for (int ns = 0; ns < 2; ns++) {
                u32 r0, r1, r2, r3;
                LDSM_X4_T(r0, r1, r2, r3, bB + ks * (16*BROWB) + ns * 32);
                fb[ns*2  ][0] = r0; fb[ns*2  ][1] = r1;
                fb[ns*2+1][0] = r2; fb[ns*2+1][1] = r3;
            }
            #pragma unroll
            for (int am = 0; am < 4; am++)
                #pragma unroll
                for (int nt = 0; nt < 4; nt++)
                    MMA_F16(acc[am][nt], fa[am], fb[nt]);
        }
    }

    const int r0 = bm + wr*64 + (lid >> 2);
    const int c0 = bn + wc*32 + (lid & 3) * 2;
    #pragma unroll
    for (int am = 0; am < 4; am++) {
        #pragma unroll
        for (int bt = 0; bt < 4; bt++) {
            const int col = c0 + bt * 8;
            const float2 bv = *(const float2*)(bias + col);
            const float alpha = QKVA ? ((col < 1024) ? 0.125f : 1.0f) : 1.0f;
            #pragma unroll
            for (int half = 0; half < 2; half++) {
                const int row = r0 + am*16 + half*8;
                float v0 = (acc[am][bt][half*2 + 0] + bv.x) * alpha;
                float v1 = (acc[am][bt][half*2 + 1] + bv.y) * alpha;
                if (RELU) { v0 = fmaxf(v0, 0.f); v1 = fmaxf(v1, 0.f); }
                if (RES) {
                    const float2 rr = *(const float2*)(res + (size_t)row * N + col);
                    v0 += rr.x; v1 += rr.y;
                }
                if (OUT == 2) {
                    *(u32*)(Cb + (size_t)row * N + col) = pack_h2(v0, v1);
                } else {
                    float2 o; o.x = v0; o.y = v1;
                    *(float2*)(C + (size_t)row * N + col) = o;
                }
            }
        }
    }
}

// ------------------------- fp16 HMMA flash attention -------------------------
// 64 q-rows per CTA, 4 warps (16 rows each), 128 threads, 4 CTAs/SM.
#define AQ_OFF   0
#define AK_OFF(st) (9216 + (st)*9216)
#define AV_OFF(st) (27648 + (st)*9216)
#define AM_OFF(st) (46080 + (st)*256)
#define ASMEM    46592

__global__ __launch_bounds__(128, 4) void attn_mma_kernel(
    const __half* __restrict__ QKV, const int* __restrict__ mask,
    __half* __restrict__ O)
{
    extern __shared__ char sm[];
    const u32 sb = smem_u32(sm);
    const int tid = threadIdx.x;
    const int wid = tid >> 5;
    const int lid = tid & 31;
    const int h = blockIdx.y;
    const int b = blockIdx.z;
    const size_t qrow0 = (size_t)(b * S_ + blockIdx.x * 64);

    const __half* Q = QKV;
    const __half* K = QKV + 1024;
    const __half* V = QKV + 2048;

    #pragma unroll
    for (int it = 0; it < 4; it++) {
        const int t = tid + it * 128;
        const int r = t >> 3, cseg = t & 7;
        const uint4 v = *(const uint4*)(Q + (qrow0 + r) * QKVN + h * 64 + cseg * 8);
        *(uint4*)(sm + AQ_OFF + r * 144 + cseg * 16) = v;
    }

    auto load_kv = [&](int jt, int st) {
        const size_t krow0 = (size_t)(b * S_ + jt * 64);
        #pragma unroll
        for (int it = 0; it < 8; it++) {
            const int t = tid + it * 128;
            const int tile = t >> 9;
            const int r = (t >> 3) & 63;
            const int cseg = t & 7;
            const __half* src = (tile ? V : K) + (krow0 + r) * QKVN + h * 64 + cseg * 8;
            const u32 dst = sb + (tile ? AV_OFF(st) : AK_OFF(st)) + (u32)(r * 144 + cseg * 16);
            CP_ASYNC16(dst, src);
        }
        if (tid < 64)
            CP_ASYNC4(sb + AM_OFF(st) + tid * 4, mask + b * S_ + jt * 64 + tid);
        CP_COMMIT();
    };

    load_kv(0, 0);
    __syncthreads();

    u32 qf[4][4];
    const u32 qaddr = sb + AQ_OFF + (u32)((wid * 16 + (lid & 15)) * 144 + (lid >> 4) * 16);
    #pragma unroll
    for (int ks = 0; ks < 4; ks++)
        LDSM_X4(qf[ks][0], qf[ks][1], qf[ks][2], qf[ks][3], qaddr + ks * 32);

    float m0 = -INFINITY, m1 = -INFINITY, l0 = 0.f, l1 = 0.f;
    float o[8][4];
    #pragma unroll
    for (int t = 0; t < 8; t++)
        #pragma unroll
        for (int f = 0; f < 4; f++) o[t][f] = 0.f;

    const int ntiles = S_ / 64;
    for (int jt = 0; jt < ntiles; jt++) {
        const int st = jt & 1;
        CP_WAIT(0);
        __syncthreads();
        if (jt + 1 < ntiles) load_kv(jt + 1, st ^ 1);

        float s[8][4];
        #pragma unroll
        for (int t = 0; t < 8; t++)
            #pragma unroll
            for (int f = 0; f < 4; f++) s[t][f] = 0.f;

        const u32 kaddr = sb + AK_OFF(st) + (u32)(((lid & 15)) * 144 + (lid >> 4) * 16);
        #pragma unroll
        for (int ks = 0; ks < 4; ks++) {
            #pragma unroll
            for (int nt2 = 0; nt2 < 4; nt2++) {
                u32 r0, r1, r2, r3;
                LDSM_X4(r0, r1, r2, r3, kaddr + nt2 * (16*144) + ks * 32);
                u32 bA[2] = {r0, r2};
                u32 bB[2] = {r1, r3};
                MMA_F16(s[nt2*2],     qf[ks], bA);
                MMA_F16(s[nt2*2 + 1], qf[ks], bB);
            }
        }

        float mx0 = -INFINITY, mx1 = -INFINITY;
        #pragma unroll
        for (int t = 0; t < 8; t++) {
            const int mi_a = *(const int*)(sm + AM_OFF(st) + (t*8 + (lid & 3)*2) * 4);
            const int mi_b = *(const int*)(sm + AM_OFF(st) + (t*8 + (lid & 3)*2 + 1) * 4);
            const float ma = mi_a ? 0.f : -1e9f;
            const float mb = mi_b ? 0.f : -1e9f;
            s[t][0] += ma; s[t][1] += mb; s[t][2] += ma; s[t][3] += mb;
            mx0 = fmaxf(mx0, fmaxf(s[t][0], s[t][1]));
            mx1 = fmaxf(mx1, fmaxf(s[t][2], s[t][3]));
        }
        mx0 = fmaxf(mx0, __shfl_xor_sync(0xffffffffu, mx0, 1));
        mx0 = fmaxf(mx0, __shfl_xor_sync(0xffffffffu, mx0, 2));
        mx1 = fmaxf(mx1, __shfl_xor_sync(0xffffffffu, mx1, 1));
        mx1 = fmaxf(mx1, __shfl_xor_sync(0xffffffffu, mx1, 2));

        const float nm0 = fmaxf(m0, mx0);
        const float nm1 = fmaxf(m1, mx1);
        const float f0 = __expf(m0 - nm0);
        const float f1 = __expf(m1 - nm1);
        m0 = nm0; m1 = nm1;
        l0 *= f0;  l1 *= f1;
        #pragma unroll
        for (int t = 0; t < 8; t++) {
            o[t][0] *= f0; o[t][1] *= f0;
            o[t][2] *= f1; o[t][3] *= f1;
        }

        u32 pa[4][4];
        float ps0 = 0.f, ps1 = 0.f;
        #pragma unroll
        for (int t = 0; t < 8; t++) {
            const float p0 = __expf(s[t][0] - m0);
            const float p1 = __expf(s[t][1] - m0);
            const float p2 = __expf(s[t][2] - m1);
            const float p3 = __expf(s[t][3] - m1);
            ps0 += p0 + p1; ps1 += p2 + p3;
            pa[t >> 1][(t & 1) * 2]     = pack_h2(p0, p1);
            pa[t >> 1][(t & 1) * 2 + 1] = pack_h2(p2, p3);
        }
        ps0 += __shfl_xor_sync(0xffffffffu, ps0, 1);
        ps0 += __shfl_xor_sync(0xffffffffu, ps0, 2);
        ps1 += __shfl_xor_sync(0xffffffffu, ps1, 1);
        ps1 += __shfl_xor_sync(0xffffffffu, ps1, 2);
        l0 += ps0; l1 += ps1;

        const u32 vaddr = sb + AV_OFF(st) + (u32)(((lid & 15)) * 144 + (lid >> 4) * 16);
        #pragma unroll
        for (int ks = 0; ks < 4; ks++) {
            #pragma unroll
            for (int dt2 = 0; dt2 < 4; dt2++) {
                u32 r0, r1, r2, r3;
                LDSM_X4_T(r0, r1, r2, r3, vaddr + ks * (16*144) + dt2 * 32);
                u32 bA[2] = {r0, r1};
                u32 bB[2] = {r2, r3};
                MMA_F16(o[dt2*2],     pa[ks], bA);
                MMA_F16(o[dt2*2 + 1], pa[ks], bB);
            }
        }
    }

    const float inv0 = (l0 > 0.f) ? 1.f / l0 : 0.f;
    const float inv1 = (l1 > 0.f) ? 1.f / l1 : 0.f;
    const size_t row0 = qrow0 + wid * 16 + (lid >> 2);
    const int colb = h * 64 + (lid & 3) * 2;
    #pragma unroll
    for (int t = 0; t < 8; t++) {
        const int col = colb + t * 8;
        *(u32*)(O + row0 * D_ + col)       = pack_h2(o[t][0] * inv0, o[t][1] * inv0);
        *(u32*)(O + (row0 + 8) * D_ + col) = pack_h2(o[t][2] * inv1, o[t][3] * inv1);
    }
}

// ------------------------- launch -------------------------------------------
extern "C" void kernel_launch(void* const* d_in, const int* in_sizes, int n_in,
                              void* d_out, int out_size)
{
    const float* x    = (const float*)d_in[0];
    const int*   mask = (const int*)  d_in[1];
    const float* wq   = (const float*)d_in[2];
    const float* bq   = (const float*)d_in[3];
    const float* wk   = (const float*)d_in[4];
    const float* bk   = (const float*)d_in[5];
    const float* wv   = (const float*)d_in[6];
    const float* bv   = (const float*)d_in[7];
    const float* wo   = (const float*)d_in[8];
    const float* bo   = (const float*)d_in[9];
    const float* g1   = (const float*)d_in[10];
    const float* be1  = (const float*)d_in[11];
    const float* g2   = (const float*)d_in[12];
    const float* be2  = (const float*)d_in[13];
    const float* w1   = (const float*)d_in[14];
    const float* bf1  = (const float*)d_in[15];
    const float* w2   = (const float*)d_in[16];
    const float* bf2  = (const float*)d_in[17];
    float* out = (float*)d_out;

    void* p;
    cudaGetSymbolAddress(&p, g_xn);     __half* xn     = (__half*)p;
    cudaGetSymbolAddress(&p, g_qkv);    __half* qkv    = (__half*)p;
    cudaGetSymbolAddress(&p, g_att);    __half* att    = (__half*)p;
    cudaGetSymbolAddress(&p, g_x2);     float*  x2     = (float*)p;
    cudaGetSymbolAddress(&p, g_h);      __half* hb     = (__half*)p;
    cudaGetSymbolAddress(&p, g_wqkv16); __half* wqkv16 = (__half*)p;
    cudaGetSymbolAddress(&p, g_bqkv);   float*  bqkv   = (float*)p;
    cudaGetSymbolAddress(&p, g_wo16);   __half* wo16   = (__half*)p;
    cudaGetSymbolAddress(&p, g_w116);   __half* w116   = (__half*)p;
    cudaGetSymbolAddress(&p, g_w216);   __half* w216   = (__half*)p;

    cudaFuncSetAttribute(h16_gemm<2,false,false,true >, cudaFuncAttributeMaxDynamicSharedMemorySize, GSMEM);
    cudaFuncSetAttribute(h16_gemm<0,false,true ,false>, cudaFuncAttributeMaxDynamicSharedMemorySize, GSMEM);
    cudaFuncSetAttribute(h16_gemm<2,true ,false,false>, cudaFuncAttributeMaxDynamicSharedMemorySize, GSMEM);
    cudaFuncSetAttribute(attn_mma_kernel, cudaFuncAttributeMaxDynamicSharedMemorySize, ASMEM);

    // critical-path prologue: wqkv convert + bias pack + LN1
    prep_kernel<<<dim3(4096, 5), 256>>>(x, g1, be1, wq, wk, wv, bq, bk, bv,
                                        wqkv16, bqkv, xn);

    // fused QKV GEMM (Q cols pre-scaled by 1/8) + tail-wave wo/w1/w2 conversion
    // 768 GEMM CTAs + 120 converter CTAs = 888 = exactly 3 waves of 296
    const dim3 gQKV(QKVN/128, M_/128 + 5);
    h16_gemm<2,false,false,true><<<gQKV, 256, GSMEM>>>(
        xn, wqkv16, bqkv, nullptr, nullptr, qkv,
        wo, w1, w2, wo16, w116, w216, M_, QKVN, D_);

    // attention: 64-q-row CTAs, 1024 total (4 CTAs/SM)
    dim3 attG(S_/64, H_, B_);
    attn_mma_kernel<<<attG, 128, ASMEM>>>(qkv, mask, att);

    // O projection + residual(x)
    const dim3 gD(D_/128, M_/128);
    h16_gemm<0,false,true,false><<<gD, 256, GSMEM>>>(
        att, wo16, bo, x, x2, nullptr,
        nullptr, nullptr, nullptr, nullptr, nullptr, nullptr, M_, D_, D_);

    ln_kernel<<<M_, 256>>>(x2, g2, be2, xn);

    const dim3 gF(F_/128, M_/128);
    h16_gemm<2,true,false,false><<<gF, 256, GSMEM>>>(
        xn, w116, bf1, nullptr, nullptr, hb,
        nullptr, nullptr, nullptr, nullptr, nullptr, nullptr, M_, F_, D_);

    h16_gemm<0,false,true,false><<<gD, 256, GSMEM>>>(
        hb, w216, bf2, x2, out, nullptr,
        nullptr, nullptr, nullptr, nullptr, nullptr, nullptr, M_, D_, F_);
}

// round 17
// speedup vs baseline: 1.0124x; 1.0027x over previous
#include <cuda_runtime.h>
#include <cuda_fp16.h>
#include <math.h>

typedef unsigned int u32;
typedef unsigned long long u64;

#define B_   2
#define S_   2048
#define D_   1024
#define H_   16
#define F_   4096
#define M_   (B_*S_)
#define QKVN 3072

// ------------------------- scratch (device globals) -------------------------
__device__ __align__(16) __half g_xn[M_*D_];
__device__ __align__(16) __half g_qkv[(size_t)M_*QKVN];
__device__ __align__(16) __half g_att[M_*D_];
__device__ __align__(16) float  g_x2[M_*D_];
__device__ __align__(16) __half g_h[(size_t)M_*F_];
__device__ __align__(16) __half g_wqkv16[(size_t)D_*QKVN];  // [K=1024][N=3072]
__device__ __align__(16) float  g_bqkv[QKVN];
__device__ __align__(16) __half g_wo16[D_*D_];              // [K][N] flat
__device__ __align__(16) __half g_w116[(size_t)D_*F_];      // flat
__device__ __align__(16) __half g_w216[(size_t)F_*D_];      // flat

// ------------------------- helpers ------------------------------------------
__device__ __forceinline__ u32 smem_u32(const void* p) {
    u32 a;
    asm("{ .reg .u64 t; cvta.to.shared.u64 t, %1; cvt.u32.u64 %0, t; }"
        : "=r"(a) : "l"(p));
    return a;
}
#define CP_ASYNC16(sm, gp) \
    asm volatile("cp.async.cg.shared.global [%0], [%1], 16;" :: "r"(sm), "l"(gp))
#define CP_ASYNC4(sm, gp) \
    asm volatile("cp.async.ca.shared.global [%0], [%1], 4;" :: "r"(sm), "l"(gp))
#define CP_COMMIT() asm volatile("cp.async.commit_group;" ::: "memory")
#define CP_WAIT(n)  asm volatile("cp.async.wait_group %0;" :: "n"(n) : "memory")

#define LDSM_X4(r0,r1,r2,r3,a) \
    asm volatile("ldmatrix.sync.aligned.m8n8.x4.shared.b16 {%0,%1,%2,%3}, [%4];" \
        : "=r"(r0), "=r"(r1), "=r"(r2), "=r"(r3) : "r"(a))
#define LDSM_X4_T(r0,r1,r2,r3,a) \
    asm volatile("ldmatrix.sync.aligned.m8n8.x4.trans.shared.b16 {%0,%1,%2,%3}, [%4];" \
        : "=r"(r0), "=r"(r1), "=r"(r2), "=r"(r3) : "r"(a))

#define MMA_F16(d, a, b) \
    asm volatile("mma.sync.aligned.m16n8k16.row.col.f32.f16.f16.f32 " \
        "{%0,%1,%2,%3}, {%4,%5,%6,%7}, {%8,%9}, {%0,%1,%2,%3};" \
        : "+f"((d)[0]), "+f"((d)[1]), "+f"((d)[2]), "+f"((d)[3]) \
        : "r"((a)[0]), "r"((a)[1]), "r"((a)[2]), "r"((a)[3]), \
          "r"((b)[0]), "r"((b)[1]))

__device__ __forceinline__ u32 pack_h2(float a, float b) {
    __half2 t = __floats2half2_rn(a, b);
    return *(u32*)&t;
}

// ------------------------- critical-path prologue ----------------------------
__global__ __launch_bounds__(256) void prep_kernel(
    const float* __restrict__ x,  const float* __restrict__ g1,
    const float* __restrict__ be1,
    const float* __restrict__ wq, const float* __restrict__ wk,
    const float* __restrict__ wv,
    const float* __restrict__ bq, const float* __restrict__ bk,
    const float* __restrict__ bv,
    __half* __restrict__ wqkv, float* __restrict__ bqkv,
    __half* __restrict__ xn)
{
    const int job = blockIdx.y;
    const int bx  = blockIdx.x;
    const int tid = threadIdx.x;

    if (job < 3) {
        if (bx >= 2048) return;
        const float* src = (job == 0) ? wq : (job == 1) ? wk : wv;
        const int colOff = job * 1024;
        for (int e = (bx * 256 + tid) * 4; e < (1 << 20); e += 2048 * 1024) {
            const float4 v = *(const float4*)(src + e);
            const int row = e >> 10;
            const int col = e & 1023;
            uint2 pk;
            pk.x = pack_h2(v.x, v.y);
            pk.y = pack_h2(v.z, v.w);
            *(uint2*)(wqkv + (size_t)row * QKVN + colOff + col) = pk;
        }
        return;
    }
    if (job == 3) {
        const int i = bx * 256 + tid;
        if (i >= QKVN) return;
        if (i < 1024)       bqkv[i] = bq[i];
        else if (i < 2048)  bqkv[i] = bk[i - 1024];
        else                bqkv[i] = bv[i - 2048];
        return;
    }

    // job == 4: LayerNorm1, row = bx
    __shared__ float red[8];
    const int row = bx;
    const float* xr = x + (size_t)row * D_;

    float4 xv = *(const float4*)(xr + tid * 4);
    float s = xv.x + xv.y + xv.z + xv.w;
    #pragma unroll
    for (int of = 16; of > 0; of >>= 1) s += __shfl_xor_sync(0xffffffffu, s, of);
    if ((tid & 31) == 0) red[tid >> 5] = s;
    __syncthreads();
    float tot = 0.f;
    #pragma unroll
    for (int w = 0; w < 8; w++) tot += red[w];
    const float mean = tot * (1.0f / D_);

    float d0 = xv.x - mean, d1 = xv.y - mean, d2 = xv.z - mean, d3 = xv.w - mean;
    float sq = d0*d0 + d1*d1 + d2*d2 + d3*d3;
    __syncthreads();
    #pragma unroll
    for (int of = 16; of > 0; of >>= 1) sq += __shfl_xor_sync(0xffffffffu, sq, of);
    if ((tid & 31) == 0) red[tid >> 5] = sq;
    __syncthreads();
    float vtot = 0.f;
    #pragma unroll
    for (int w = 0; w < 8; w++) vtot += red[w];
    const float rstd = rsqrtf(vtot * (1.0f / D_) + 1e-5f);

    float4 gv = *(const float4*)(g1 + tid * 4);
    float4 bv4 = *(const float4*)(be1 + tid * 4);
    const size_t off = (size_t)row * D_ + tid * 4;
    uint2 pk;
    pk.x = pack_h2(d0 * rstd * gv.x + bv4.x, d1 * rstd * gv.y + bv4.y);
    pk.y = pack_h2(d2 * rstd * gv.z + bv4.z, d3 * rstd * gv.w + bv4.w);
    *(uint2*)(xn + off) = pk;
}

// ------------------------- layernorm (fp16 out) ------------------------------
__global__ __launch_bounds__(256) void ln_kernel(
    const float* __restrict__ x, const float* __restrict__ g,
    const float* __restrict__ b, __half* __restrict__ o)
{
    __shared__ float red[8];
    const int row = blockIdx.x;
    const int tid = threadIdx.x;
    const float* xr = x + (size_t)row * D_;

    float4 xv = *(const float4*)(xr + tid * 4);
    float s = xv.x + xv.y + xv.z + xv.w;
    #pragma unroll
    for (int of = 16; of > 0; of >>= 1) s += __shfl_xor_sync(0xffffffffu, s, of);
    if ((tid & 31) == 0) red[tid >> 5] = s;
    __syncthreads();
    float tot = 0.f;
    #pragma unroll
    for (int w = 0; w < 8; w++) tot += red[w];
    const float mean = tot * (1.0f / D_);

    float d0 = xv.x - mean, d1 = xv.y - mean, d2 = xv.z - mean, d3 = xv.w - mean;
    float sq = d0*d0 + d1*d1 + d2*d2 + d3*d3;
    __syncthreads();
    #pragma unroll
    for (int of = 16; of > 0; of >>= 1) sq += __shfl_xor_sync(0xffffffffu, sq, of);
    if ((tid & 31) == 0) red[tid >> 5] = sq;
    __syncthreads();
    float vtot = 0.f;
    #pragma unroll
    for (int w = 0; w < 8; w++) vtot += red[w];
    const float rstd = rsqrtf(vtot * (1.0f / D_) + 1e-5f);

    float4 gv = *(const float4*)(g + tid * 4);
    float4 bv = *(const float4*)(b + tid * 4);
    const size_t off = (size_t)row * D_ + tid * 4;
    uint2 pk;
    pk.x = pack_h2(d0 * rstd * gv.x + bv.x, d1 * rstd * gv.y + bv.y);
    pk.y = pack_h2(d2 * rstd * gv.z + bv.z, d3 * rstd * gv.w + bv.w);
    *(uint2*)(o + off) = pk;
}

// ------------------------- fp16 HMMA GEMM (256 thr, 128x128 tile) ------------
#define ATROWB 144
#define ATILE  (128*ATROWB)        // 18432
#define BROWB  272
#define BTILE  (64*BROWB)          // 17408
#define STAGEB (ATILE + BTILE)     // 35840
#define GSMEM  (2*STAGEB)          // 71680
#define NCONV  120

template<int OUT, bool RELU, bool RES, bool QKVA>
__global__ __launch_bounds__(256, 2) void h16_gemm(
    const __half* __restrict__ A, const __half* __restrict__ Bw,
    const float* __restrict__ bias, const float* __restrict__ res,
    float* __restrict__ C, __half* __restrict__ Cb,
    const float* __restrict__ cw0, const float* __restrict__ cw1,
    const float* __restrict__ cw2,
    __half* __restrict__ cd0, __half* __restrict__ cd1,
    __half* __restrict__ cd2,
    int M, int N, int K)
{
    extern __shared__ char smem[];
    const u32 sbase = smem_u32(smem);

    const int tid = threadIdx.x;

    if (QKVA && (int)blockIdx.y >= (M >> 7)) {
        const int cb   = ((int)blockIdx.y - (M >> 7)) * gridDim.x + blockIdx.x;
        if (cb >= NCONV) return;
        const int step = NCONV * 256 * 4;
        const int t0   = (cb * 256 + tid) * 4;
        for (int e = t0; e < (1 << 20); e += step) {
            const float4 v = *(const float4*)(cw0 + e);
            uint2 pk; pk.x = pack_h2(v.x, v.y); pk.y = pack_h2(v.z, v.w);
            *(uint2*)(cd0 + e) = pk;
        }
        for (int e = t0; e < (1 << 22); e += step) {
            const float4 v = *(const float4*)(cw1 + e);
            uint2 pk; pk.x = pack_h2(v.x, v.y); pk.y = pack_h2(v.z, v.w);
            *(uint2*)(cd1 + e) = pk;
        }
        for (int e = t0; e < (1 << 22); e += step) {
            const float4 v = *(const float4*)(cw2 + e);
            uint2 pk; pk.x = pack_h2(v.x, v.y); pk.y = pack_h2(v.z, v.w);
            *(uint2*)(cd2 + e) = pk;
        }
        return;
    }

    const int wid = tid >> 5;
    const int lid = tid & 31;
    const int wr  = wid & 1;
    const int wc  = wid >> 1;
    const int bm  = blockIdx.y * 128;
    const int bn  = blockIdx.x * 128;

    const int nch = K >> 6;

    auto load_chunk = [&](int i, int st) {
        const size_t kc = (size_t)i * 64;
        const u32 so = sbase + st * STAGEB;
        #pragma unroll
        for (int it = 0; it < 4; it++) {
            const int idx = tid + it * 256;
            const int r = idx >> 3, seg = idx & 7;
            const __half* gp = A + (size_t)(bm + r) * K + kc + seg * 8;
            CP_ASYNC16(so + r * ATROWB + seg * 16, gp);
        }
        #pragma unroll
        for (int it = 0; it < 4; it++) {
            const int idx = tid + it * 256;
            const int r = idx >> 4, seg = idx & 15;
            const __half* gp = Bw + (kc + r) * (size_t)N + bn + seg * 8;
            CP_ASYNC16(so + ATILE + r * BROWB + seg * 16, gp);
        }
        CP_COMMIT();
    };

    float acc[4][4][4];
    #pragma unroll
    for (int i = 0; i < 4; i++)
        #pragma unroll
        for (int j = 0; j < 4; j++)
            #pragma unroll
            for (int f = 0; f < 4; f++) acc[i][j][f] = 0.f;

    const u32 a_lane = (u32)((wr*64 + (lid & 15)) * ATROWB + (lid >> 4) * 16);
    const u32 b_lane = (u32)((lid & 15) * BROWB + (lid >> 4) * 16 + wc * 64);

    load_chunk(0, 0);

    for (int i = 0; i < nch; i++) {
        const int st = i & 1;
        CP_WAIT(0);
        __syncthreads();
        if (i + 1 < nch) load_chunk(i + 1, st ^ 1);

        const u32 so = sbase + st * STAGEB;
        const u32 aB = so + a_lane;
        const u32 bB = so + ATILE + b_lane;

        #pragma unroll
        for (int ks = 0; ks < 4; ks++) {
            u32 fa[4][4];
            #pragma unroll
            for (int am = 0; am < 4; am++)
                LDSM_X4(fa[am][0], fa[am][1], fa[am][2], fa[am][3],
                        aB + am * (16*ATROWB) + ks * 32);
            u32 fb[4][2];
            #pragma unroll
            for (int ns = 0; ns < 2; ns++) {
                u32 r0, r1, r2, r3;
                LDSM_X4_T(r0, r1, r2, r3, bB + ks * (16*BROWB) + ns * 32);
                fb[ns*2  ][0] = r0; fb[ns*2  ][1] = r1;
                fb[ns*2+1][0] = r2; fb[ns*2+1][1] = r3;
            }
            #pragma unroll
            for (int am = 0; am < 4; am++)
                #pragma unroll
                for (int nt = 0; nt < 4; nt++)
                    MMA_F16(acc[am][nt], fa[am], fb[nt]);
        }
    }

    const int r0 = bm + wr*64 + (lid >> 2);
    const int c0 = bn + wc*32 + (lid & 3) * 2;
    #pragma unroll
    for (int am = 0; am < 4; am++) {
        #pragma unroll
        for (int bt = 0; bt < 4; bt++) {
            const int col = c0 + bt * 8;
            const float2 bv = *(const float2*)(bias + col);
            const float alpha = QKVA ? ((col < 1024) ? 0.125f : 1.0f) : 1.0f;
            #pragma unroll
            for (int half = 0; half < 2; half++) {
                const int row = r0 + am*16 + half*8;
                float v0 = (acc[am][bt][half*2 + 0] + bv.x) * alpha;
                float v1 = (acc[am][bt][half*2 + 1] + bv.y) * alpha;
                if (RELU) { v0 = fmaxf(v0, 0.f); v1 = fmaxf(v1, 0.f); }
                if (RES) {
                    const float2 rr = *(const float2*)(res + (size_t)row * N + col);
                    v0 += rr.x; v1 += rr.y;
                }
                if (OUT == 2) {
                    *(u32*)(Cb + (size_t)row * N + col) = pack_h2(v0, v1);
                } else {
                    float2 o; o.x = v0; o.y = v1;
                    *(float2*)(C + (size_t)row * N + col) = o;
                }
            }
        }
    }
}

// ------------------------- fp16 HMMA flash attention -------------------------
// 64 q-rows/CTA, 4 warps, 128 threads, 4 CTAs/SM.
// 3-stage KV ring (CP_WAIT(1), two tiles in flight); Q staged in stage 2's
// region (consumed into registers before stage 2 is first written).
#define AKS_OFF(st) ((st)*18432)
#define AVS_OFF(st) ((st)*18432 + 9216)
#define AMS_OFF(st) (55296 + (st)*256)
#define AQS_OFF     36864            // overlay on stage 2
#define ASMEM       56064

__global__ __launch_bounds__(128, 4) void attn_mma_kernel(
    const __half* __restrict__ QKV, const int* __restrict__ mask,
    __half* __restrict__ O)
{
    extern __shared__ char sm[];
    const u32 sb = smem_u32(sm);
    const int tid = threadIdx.x;
    const int wid = tid >> 5;
    const int lid = tid & 31;
    const int h = blockIdx.y;
    const int b = blockIdx.z;
    const size_t qrow0 = (size_t)(b * S_ + blockIdx.x * 64);

    const __half* Q = QKV;
    const __half* K = QKV + 1024;
    const __half* V = QKV + 2048;

    // stage Q tile (64 x 64 fp16) into stage-2 region
    #pragma unroll
    for (int it = 0; it < 4; it++) {
        const int t = tid + it * 128;
        const int r = t >> 3, cseg = t & 7;
        const uint4 v = *(const uint4*)(Q + (qrow0 + r) * QKVN + h * 64 + cseg * 8);
        *(uint4*)(sm + AQS_OFF + r * 144 + cseg * 16) = v;
    }

    auto load_kv = [&](int jt, int st) {
        const size_t krow0 = (size_t)(b * S_ + jt * 64);
        #pragma unroll
        for (int it = 0; it < 8; it++) {
            const int t = tid + it * 128;
            const int tile = t >> 9;
            const int r = (t >> 3) & 63;
            const int cseg = t & 7;
            const __half* src = (tile ? V : K) + (krow0 + r) * QKVN + h * 64 + cseg * 8;
            const u32 dst = sb + (tile ? AVS_OFF(st) : AKS_OFF(st)) + (u32)(r * 144 + cseg * 16);
            CP_ASYNC16(dst, src);
        }
        if (tid < 64)
            CP_ASYNC4(sb + AMS_OFF(st) + tid * 4, mask + b * S_ + jt * 64 + tid);
        CP_COMMIT();
    };

    // prefetch tiles 0 and 1 (stages 0,1 — disjoint from Q overlay)
    load_kv(0, 0);
    load_kv(1, 1);
    __syncthreads();   // Q staging visible

    u32 qf[4][4];
    const u32 qaddr = sb + AQS_OFF + (u32)((wid * 16 + (lid & 15)) * 144 + (lid >> 4) * 16);
    #pragma unroll
    for (int ks = 0; ks < 4; ks++)
        LDSM_X4(qf[ks][0], qf[ks][1], qf[ks][2], qf[ks][3], qaddr + ks * 32);

    float m0 = -INFINITY, m1 = -INFINITY, l0 = 0.f, l1 = 0.f;
    float o[8][4];
    #pragma unroll
    for (int t = 0; t < 8; t++)
        #pragma unroll
        for (int f = 0; f < 4; f++) o[t][f] = 0.f;

    const int ntiles = S_ / 64;
    for (int jt = 0; jt < ntiles; jt++) {
        const int st = jt % 3;
        if (jt + 1 < ntiles) { CP_WAIT(1); } else { CP_WAIT(0); }
        __syncthreads();
        if (jt + 2 < ntiles) load_kv(jt + 2, (jt + 2) % 3);

        float s[8][4];
        #pragma unroll
        for (int t = 0; t < 8; t++)
            #pragma unroll
            for (int f = 0; f < 4; f++) s[t][f] = 0.f;

        const u32 kaddr = sb + AKS_OFF(st) + (u32)(((lid & 15)) * 144 + (lid >> 4) * 16);
        #pragma unroll
        for (int ks = 0; ks < 4; ks++) {
            #pragma unroll
            for (int nt2 = 0; nt2 < 4; nt2++) {
                u32 r0, r1, r2, r3;
                LDSM_X4(r0, r1, r2, r3, kaddr + nt2 * (16*144) + ks * 32);
                u32 bA[2] = {r0, r2};
                u32 bB[2] = {r1, r3};
                MMA_F16(s[nt2*2],     qf[ks], bA);
                MMA_F16(s[nt2*2 + 1], qf[ks], bB);
            }
        }

        float mx0 = -INFINITY, mx1 = -INFINITY;
        #pragma unroll
        for (int t = 0; t < 8; t++) {
            const int mi_a = *(const int*)(sm + AMS_OFF(st) + (t*8 + (lid & 3)*2) * 4);
            const int mi_b = *(const int*)(sm + AMS_OFF(st) + (t*8 + (lid & 3)*2 + 1) * 4);
            const float ma = mi_a ? 0.f : -1e9f;
            const float mb = mi_b ? 0.f : -1e9f;
            s[t][0] += ma; s[t][1] += mb; s[t][2] += ma; s[t][3] += mb;
            mx0 = fmaxf(mx0, fmaxf(s[t][0], s[t][1]));
            mx1 = fmaxf(mx1, fmaxf(s[t][2], s[t][3]));
        }
        mx0 = fmaxf(mx0, __shfl_xor_sync(0xffffffffu, mx0, 1));
        mx0 = fmaxf(mx0, __shfl_xor_sync(0xffffffffu, mx0, 2));
        mx1 = fmaxf(mx1, __shfl_xor_sync(0xffffffffu, mx1, 1));
        mx1 = fmaxf(mx1, __shfl_xor_sync(0xffffffffu, mx1, 2));

        const float nm0 = fmaxf(m0, mx0);
        const float nm1 = fmaxf(m1, mx1);
        const float f0 = __expf(m0 - nm0);
        const float f1 = __expf(m1 - nm1);
        m0 = nm0; m1 = nm1;
        l0 *= f0;  l1 *= f1;
        #pragma unroll
        for (int t = 0; t < 8; t++) {
            o[t][0] *= f0; o[t][1] *= f0;
            o[t][2] *= f1; o[t][3] *= f1;
        }

        u32 pa[4][4];
        float ps0 = 0.f, ps1 = 0.f;
        #pragma unroll
        for (int t = 0; t < 8; t++) {
            const float p0 = __expf(s[t][0] - m0);
            const float p1 = __expf(s[t][1] - m0);
            const float p2 = __expf(s[t][2] - m1);
            const float p3 = __expf(s[t][3] - m1);
            ps0 += p0 + p1; ps1 += p2 + p3;
            pa[t >> 1][(t & 1) * 2]     = pack_h2(p0, p1);
            pa[t >> 1][(t & 1) * 2 + 1] = pack_h2(p2, p3);
        }
        ps0 += __shfl_xor_sync(0xffffffffu, ps0, 1);
        ps0 += __shfl_xor_sync(0xffffffffu, ps0, 2);
        ps1 += __shfl_xor_sync(0xffffffffu, ps1, 1);
        ps1 += __shfl_xor_sync(0xffffffffu, ps1, 2);
        l0 += ps0; l1 += ps1;

        const u32 vaddr = sb + AVS_OFF(st) + (u32)(((lid & 15)) * 144 + (lid >> 4) * 16);
        #pragma unroll
        for (int ks = 0; ks < 4; ks++) {
            #pragma unroll
            for (int dt2 = 0; dt2 < 4; dt2++) {
                u32 r0, r1, r2, r3;
                LDSM_X4_T(r0, r1, r2, r3, vaddr + ks * (16*144) + dt2 * 32);
                u32 bA[2] = {r0, r1};
                u32 bB[2] = {r2, r3};
                MMA_F16(o[dt2*2],     pa[ks], bA);
                MMA_F16(o[dt2*2 + 1], pa[ks], bB);
            }
        }
    }

    const float inv0 = (l0 > 0.f) ? 1.f / l0 : 0.f;
    const float inv1 = (l1 > 0.f) ? 1.f / l1 : 0.f;
    const size_t row0 = qrow0 + wid * 16 + (lid >> 2);
    const int colb = h * 64 + (lid & 3) * 2;
    #pragma unroll
    for (int t = 0; t < 8; t++) {
        const int col = colb + t * 8;
        *(u32*)(O + row0 * D_ + col)       = pack_h2(o[t][0] * inv0, o[t][1] * inv0);
        *(u32*)(O + (row0 + 8) * D_ + col) = pack_h2(o[t][2] * inv1, o[t][3] * inv1);
    }
}

// ------------------------- launch -------------------------------------------
extern "C" void kernel_launch(void* const* d_in, const int* in_sizes, int n_in,
                              void* d_out, int out_size)
{
    const float* x    = (const float*)d_in[0];
    const int*   mask = (const int*)  d_in[1];
    const float* wq   = (const float*)d_in[2];
    const float* bq   = (const float*)d_in[3];
    const float* wk   = (const float*)d_in[4];
    const float* bk   = (const float*)d_in[5];
    const float* wv   = (const float*)d_in[6];
    const float* bv   = (const float*)d_in[7];
    const float* wo   = (const float*)d_in[8];
    const float* bo   = (const float*)d_in[9];
    const float* g1   = (const float*)d_in[10];
    const float* be1  = (const float*)d_in[11];
    const float* g2   = (const float*)d_in[12];
    const float* be2  = (const float*)d_in[13];
    const float* w1   = (const float*)d_in[14];
    const float* bf1  = (const float*)d_in[15];
    const float* w2   = (const float*)d_in[16];
    const float* bf2  = (const float*)d_in[17];
    float* out = (float*)d_out;

    void* p;
    cudaGetSymbolAddress(&p, g_xn);     __half* xn     = (__half*)p;
    cudaGetSymbolAddress(&p, g_qkv);    __half* qkv    = (__half*)p;
    cudaGetSymbolAddress(&p, g_att);    __half* att    = (__half*)p;
    cudaGetSymbolAddress(&p, g_x2);     float*  x2     = (float*)p;
    cudaGetSymbolAddress(&p, g_h);      __half* hb     = (__half*)p;
    cudaGetSymbolAddress(&p, g_wqkv16); __half* wqkv16 = (__half*)p;
    cudaGetSymbolAddress(&p, g_bqkv);   float*  bqkv   = (float*)p;
    cudaGetSymbolAddress(&p, g_wo16);   __half* wo16   = (__half*)p;
    cudaGetSymbolAddress(&p, g_w116);   __half* w116   = (__half*)p;
    cudaGetSymbolAddress(&p, g_w216);   __half* w216   = (__half*)p;

    cudaFuncSetAttribute(h16_gemm<2,false,false,true >, cudaFuncAttributeMaxDynamicSharedMemorySize, GSMEM);
    cudaFuncSetAttribute(h16_gemm<0,false,true ,false>, cudaFuncAttributeMaxDynamicSharedMemorySize, GSMEM);
    cudaFuncSetAttribute(h16_gemm<2,true ,false,false>, cudaFuncAttributeMaxDynamicSharedMemorySize, GSMEM);
    cudaFuncSetAttribute(attn_mma_kernel, cudaFuncAttributeMaxDynamicSharedMemorySize, ASMEM);

    // critical-path prologue: wqkv convert + bias pack + LN1
    prep_kernel<<<dim3(4096, 5), 256>>>(x, g1, be1, wq, wk, wv, bq, bk, bv,
                                        wqkv16, bqkv, xn);

    // fused QKV GEMM (Q cols pre-scaled by 1/8) + tail-wave wo/w1/w2 conversion
    const dim3 gQKV(QKVN/128, M_/128 + 5);
    h16_gemm<2,false,false,true><<<gQKV, 256, GSMEM>>>(
        xn, wqkv16, bqkv, nullptr, nullptr, qkv,
        wo, w1, w2, wo16, w116, w216, M_, QKVN, D_);

    // attention: 64-q-row CTAs, 1024 total (4 CTAs/SM), 3-stage KV ring
    dim3 attG(S_/64, H_, B_);
    attn_mma_kernel<<<attG, 128, ASMEM>>>(qkv, mask, att);

    // O projection + residual(x)
    const dim3 gD(D_/128, M_/128);
    h16_gemm<0,false,true,false><<<gD, 256, GSMEM>>>(
        att, wo16, bo, x, x2, nullptr,
        nullptr, nullptr, nullptr, nullptr, nullptr, nullptr, M_, D_, D_);

    ln_kernel<<<M_, 256>>>(x2, g2, be2, xn);

    const dim3 gF(F_/128, M_/128);
    h16_gemm<2,true,false,false><<<gF, 256, GSMEM>>>(
        xn, w116, bf1, nullptr, nullptr, hb,
        nullptr, nullptr, nullptr, nullptr, nullptr, nullptr, M_, F_, D_);

    h16_gemm<0,false,true,false><<<gD, 256, GSMEM>>>(
        hb, w216, bf2, x2, out, nullptr,
        nullptr, nullptr, nullptr, nullptr, nullptr, nullptr, M_, D_, F_);
}